// round 15
// baseline (speedup 1.0000x reference)
#include <cuda_runtime.h>
#include <cuda_bf16.h>
#include <cstdint>

#define NUM_GRIDS 8

__device__ __forceinline__ float tanh_approx(float x) {
    float y;
    asm("tanh.approx.f32 %0, %1;" : "=f"(y) : "f"(x));
    return y;
}

__device__ __forceinline__ float bump(float xi, float g) {
    const float th = tanh_approx(xi - g);
    return 1.0f - th * th;
}

// Default write-back policy (no .cs): let L2 accumulate full dirty lines and
// drain in large batches instead of evict-first's eager small writebacks.
__device__ __forceinline__ void stg256_wb(float* dst,
                                          float r0, float r1, float r2, float r3,
                                          float r4, float r5, float r6, float r7) {
    asm volatile(
        "st.global.v8.f32 [%0], {%1,%2,%3,%4,%5,%6,%7,%8};"
        :: "l"(dst),
           "f"(r0), "f"(r1), "f"(r2), "f"(r3),
           "f"(r4), "f"(r5), "f"(r6), "f"(r7)
        : "memory");
}

// Best-measured shape (R9): flat grid, 2 elements/thread.
// 1x LDG.64 in (warp = 256 B contiguous), 16 outputs via 2x STG.256
// (warp = 2 KB contiguous). All results in named scalars, regs ~27.
__global__ __launch_bounds__(256)
void rswaf_kernel(const float2* __restrict__ x,
                  const float4* __restrict__ grid,   // [8] floats = 2 float4
                  const float*  __restrict__ inv_den,
                  float*        __restrict__ out,
                  int n2) {
    const int i = blockIdx.x * blockDim.x + threadIdx.x;
    if (i >= n2) return;

    const float inv = __ldg(inv_den);

    // pre-scale grid by inv: (x-g)*inv = x*inv - g*inv
    const float4 gA = __ldg(grid + 0);
    const float4 gB = __ldg(grid + 1);
    const float g0 = gA.x * inv, g1 = gA.y * inv, g2 = gA.z * inv, g3 = gA.w * inv;
    const float g4 = gB.x * inv, g5 = gB.y * inv, g6 = gB.z * inv, g7 = gB.w * inv;

    const float2 xv = __ldcs(x + i);     // read stream: evict-first is right
    const float xa = xv.x * inv;
    const float xb = xv.y * inv;

    float* dst = out + (long long)i * (2 * NUM_GRIDS);

    stg256_wb(dst,
              bump(xa, g0), bump(xa, g1), bump(xa, g2), bump(xa, g3),
              bump(xa, g4), bump(xa, g5), bump(xa, g6), bump(xa, g7));

    stg256_wb(dst + NUM_GRIDS,
              bump(xb, g0), bump(xb, g1), bump(xb, g2), bump(xb, g3),
              bump(xb, g4), bump(xb, g5), bump(xb, g6), bump(xb, g7));
}

extern "C" void kernel_launch(void* const* d_in, const int* in_sizes, int n_in,
                              void* d_out, int out_size) {
    const float* x       = (const float*)d_in[0];   // [16,64,128,128] fp32
    const float* grid    = (const float*)d_in[1];   // [8] fp32
    const float* inv_den = (const float*)d_in[2];   // scalar fp32
    float* out = (float*)d_out;                     // [...,8] fp32

    const int n  = in_sizes[0];        // 16,777,216 (even)
    const int n2 = n >> 1;             // 8,388,608 float2s

    const int threads = 256;
    const int blocks  = (n2 + threads - 1) / threads;   // 32768

    rswaf_kernel<<<blocks, threads>>>(
        (const float2*)x, (const float4*)grid, inv_den, out, n2);
}

// round 16
// speedup vs baseline: 1.0031x; 1.0031x over previous
#include <cuda_runtime.h>
#include <cuda_bf16.h>
#include <cstdint>

#define NUM_GRIDS 8

// Precomputed per-launch constants: c[j] = -grid[j]*inv, c[8] = inv.
// __device__ global = static allocation (legal under _HX_ENFORCE).
__device__ float g_coef[12];

__global__ void rswaf_setup(const float* __restrict__ grid,
                            const float* __restrict__ inv_den) {
    const float inv = *inv_den;
#pragma unroll
    for (int j = 0; j < NUM_GRIDS; j++)
        g_coef[j] = -grid[j] * inv;
    g_coef[8]  = inv;
    g_coef[9]  = 0.f;
    g_coef[10] = 0.f;
    g_coef[11] = 0.f;
}

__device__ __forceinline__ float tanh_approx(float x) {
    float y;
    asm("tanh.approx.f32 %0, %1;" : "=f"(y) : "f"(x));
    return y;
}

// th = tanh(fma(x, inv, -g*inv)); out = 1 - th*th
__device__ __forceinline__ float bump_fma(float x, float inv, float negGI) {
    const float th = tanh_approx(fmaf(x, inv, negGI));
    return 1.0f - th * th;
}

// Best-measured memory shape (R6): one thread per input element,
// 1x LDG.32 in (warp = 128 B coalesced), 8 outputs via 1x STG.256
// (warp = 1024 B contiguous). Constants preloaded by setup kernel:
// per-thread overhead is 2 broadcast LDG.128 (L1-resident) only.
__global__ __launch_bounds__(256)
void rswaf_kernel(const float* __restrict__ x,
                  float*       __restrict__ out,
                  int n) {
    const int e = blockIdx.x * blockDim.x + threadIdx.x;
    if (e >= n) return;

    const float4 c0 = *(const float4*)(g_coef + 0);   // -g0..3*inv
    const float4 c1 = *(const float4*)(g_coef + 4);   // -g4..7*inv
    const float  iv = g_coef[8];

    const float xi = __ldcs(x + e);

    const float r0 = bump_fma(xi, iv, c0.x);
    const float r1 = bump_fma(xi, iv, c0.y);
    const float r2 = bump_fma(xi, iv, c0.z);
    const float r3 = bump_fma(xi, iv, c0.w);
    const float r4 = bump_fma(xi, iv, c1.x);
    const float r5 = bump_fma(xi, iv, c1.y);
    const float r6 = bump_fma(xi, iv, c1.z);
    const float r7 = bump_fma(xi, iv, c1.w);

    float* dst = out + (long long)e * NUM_GRIDS;      // 32B-aligned
    asm volatile(
        "st.global.cs.v8.f32 [%0], {%1,%2,%3,%4,%5,%6,%7,%8};"
        :: "l"(dst),
           "f"(r0), "f"(r1), "f"(r2), "f"(r3),
           "f"(r4), "f"(r5), "f"(r6), "f"(r7)
        : "memory");
}

extern "C" void kernel_launch(void* const* d_in, const int* in_sizes, int n_in,
                              void* d_out, int out_size) {
    const float* x       = (const float*)d_in[0];   // [16,64,128,128] fp32
    const float* grid    = (const float*)d_in[1];   // [8] fp32
    const float* inv_den = (const float*)d_in[2];   // scalar fp32
    float* out = (float*)d_out;                     // [...,8] fp32

    const int n = in_sizes[0];                      // 16,777,216

    rswaf_setup<<<1, 1>>>(grid, inv_den);

    const int threads = 256;
    const int blocks  = (n + threads - 1) / threads;   // 65536
    rswaf_kernel<<<blocks, threads>>>(x, out, n);
}